// round 1
// baseline (speedup 1.0000x reference)
#include <cuda_runtime.h>

#define N_PLANES 73
#define BOARD 8
#define FLAT (N_PLANES * BOARD * BOARD)   // 4672
#define N_MOVES 1858
#define BATCH 4096

// Scratch for the extracted one-hot row indices (no device mallocs allowed).
__device__ int g_idx[N_MOVES];

// ---------------------------------------------------------------------------
// Kernel 1: recover idx[j] = r such that W[r][j] == 1.0, by scanning the
// dense [FLAT, N_MOVES] matrix with coalesced float4 loads. Only the rare
// nonzero lanes pay for the div/mod.
// FLAT*N_MOVES = 8,680,576 elements = 2,170,144 float4s (exactly divisible).
// ---------------------------------------------------------------------------
__global__ void extract_idx_kernel(const float4* __restrict__ W4,
                                   int* __restrict__ idx, int n4) {
    int i = blockIdx.x * blockDim.x + threadIdx.x;
    if (i >= n4) return;
    float4 v = W4[i];
    if (v.x != 0.f || v.y != 0.f || v.z != 0.f || v.w != 0.f) {
        long e = (long)i * 4;
        if (v.x != 0.f) { long t = e + 0; idx[t % N_MOVES] = (int)(t / N_MOVES); }
        if (v.y != 0.f) { long t = e + 1; idx[t % N_MOVES] = (int)(t / N_MOVES); }
        if (v.z != 0.f) { long t = e + 2; idx[t % N_MOVES] = (int)(t / N_MOVES); }
        if (v.w != 0.f) { long t = e + 3; idx[t % N_MOVES] = (int)(t / N_MOVES); }
    }
}

// ---------------------------------------------------------------------------
// Kernel 2: per batch row — coalesced float4 load of the 4672-float row into
// shared memory, then coalesced gather-writes to the 1858 outputs.
// FLAT = 4672 floats = 1168 float4s.
// ---------------------------------------------------------------------------
__global__ __launch_bounds__(256)
void gather_kernel(const float* __restrict__ x,
                   const int* __restrict__ idx,
                   float* __restrict__ out) {
    __shared__ float row[FLAT];

    int b = blockIdx.x;
    const float4* xr = (const float4*)(x + (size_t)b * FLAT);
    float4* rs = (float4*)row;
    #pragma unroll
    for (int i = threadIdx.x; i < FLAT / 4; i += 256) {
        rs[i] = xr[i];
    }
    __syncthreads();

    float* ob = out + (size_t)b * N_MOVES;
    for (int j = threadIdx.x; j < N_MOVES; j += 256) {
        ob[j] = row[idx[j]];
    }
}

extern "C" void kernel_launch(void* const* d_in, const int* in_sizes, int n_in,
                              void* d_out, int out_size) {
    const float* x = (const float*)d_in[0];          // [4096, 73, 8, 8]
    const float* W = (const float*)d_in[1];          // [4672, 1858]
    float* out = (float*)d_out;                      // [4096, 1858]

    int* idx_ptr;
    cudaGetSymbolAddress((void**)&idx_ptr, g_idx);

    const int n4 = (FLAT * N_MOVES) / 4;             // 2,170,144
    extract_idx_kernel<<<(n4 + 255) / 256, 256>>>((const float4*)W, idx_ptr, n4);
    gather_kernel<<<BATCH, 256>>>(x, idx_ptr, out);
}

// round 3
// speedup vs baseline: 1.1735x; 1.1735x over previous
#include <cuda_runtime.h>

#define N_PLANES 73
#define BOARD 8
#define FLAT (N_PLANES * BOARD * BOARD)   // 4672
#define N_MOVES 1858
#define NM2 (N_MOVES / 2)                 // 929
#define BATCH 4096
#define ROWS 2                            // batch rows per gather block

// Scratch for extracted one-hot row indices (device mallocs banned).
// 16B-aligned so it can be read as int2/int4.
__device__ __align__(16) int g_idx[N_MOVES];

// ---------------------------------------------------------------------------
// Kernel 1: recover idx[j] = r with W[r][j] == 1.0. Grid-stride scan with
// 4-way ILP, streaming loads (W has zero reuse). Only the ~1858 nonzero
// lanes pay the div/mod.
// ---------------------------------------------------------------------------
__global__ __launch_bounds__(256)
void extract_idx_kernel(const float4* __restrict__ W4,
                        int* __restrict__ idx, int n4) {
    int tid    = blockIdx.x * blockDim.x + threadIdx.x;
    int stride = gridDim.x * blockDim.x;

    for (int base = tid; base < n4; base += 4 * stride) {
        int i0 = base;
        int i1 = base + stride;
        int i2 = base + 2 * stride;
        int i3 = base + 3 * stride;
        float4 v0 = __ldcs(&W4[i0]);
        float4 v1 = (i1 < n4) ? __ldcs(&W4[i1]) : make_float4(0.f, 0.f, 0.f, 0.f);
        float4 v2 = (i2 < n4) ? __ldcs(&W4[i2]) : make_float4(0.f, 0.f, 0.f, 0.f);
        float4 v3 = (i3 < n4) ? __ldcs(&W4[i3]) : make_float4(0.f, 0.f, 0.f, 0.f);

        #define CHECK4(v, ii)                                                    \
            if (v.x != 0.f || v.y != 0.f || v.z != 0.f || v.w != 0.f) {          \
                long e = (long)(ii) * 4;                                         \
                if (v.x != 0.f) { long t = e;     idx[t % N_MOVES] = (int)(t / N_MOVES); } \
                if (v.y != 0.f) { long t = e + 1; idx[t % N_MOVES] = (int)(t / N_MOVES); } \
                if (v.z != 0.f) { long t = e + 2; idx[t % N_MOVES] = (int)(t / N_MOVES); } \
                if (v.w != 0.f) { long t = e + 3; idx[t % N_MOVES] = (int)(t / N_MOVES); } \
            }
        CHECK4(v0, i0)
        CHECK4(v1, i1)
        CHECK4(v2, i2)
        CHECK4(v3, i3)
        #undef CHECK4
    }
}

// ---------------------------------------------------------------------------
// Kernel 2: each block handles ROWS consecutive batch rows.
// Rows are contiguous in x and out, so the smem fill is one contiguous
// float4 stream and writes are one contiguous float2 stream.
// ---------------------------------------------------------------------------
__global__ __launch_bounds__(256)
void gather_kernel(const float* __restrict__ x,
                   const int* __restrict__ idx,
                   float* __restrict__ out) {
    __shared__ float rows[ROWS * FLAT];   // 2*4672*4 = 37376 B

    size_t b0 = (size_t)blockIdx.x * ROWS;

    // Contiguous fill of ROWS rows: ROWS*FLAT/4 float4s.
    const float4* xr = (const float4*)(x + b0 * FLAT);
    float4* rs = (float4*)rows;
    #pragma unroll
    for (int i = threadIdx.x; i < ROWS * FLAT / 4; i += 256) {
        rs[i] = __ldcs(&xr[i]);
    }
    __syncthreads();

    // Contiguous float2 writes: ROWS*NM2 per block.
    const int2* idx2 = (const int2*)idx;
    float2* ob = (float2*)(out + b0 * N_MOVES);
    #pragma unroll
    for (int j = threadIdx.x; j < ROWS * NM2; j += 256) {
        int r  = j / NM2;                 // which of the ROWS rows
        int jj = j - r * NM2;
        int2 p = __ldg(&idx2[jj]);
        int base = r * FLAT;
        ob[j] = make_float2(rows[base + p.x], rows[base + p.y]);
    }
}

extern "C" void kernel_launch(void* const* d_in, const int* in_sizes, int n_in,
                              void* d_out, int out_size) {
    const float* x = (const float*)d_in[0];          // [4096, 73, 8, 8]
    const float* W = (const float*)d_in[1];          // [4672, 1858]
    float* out = (float*)d_out;                      // [4096, 1858]

    int* idx_ptr;
    cudaGetSymbolAddress((void**)&idx_ptr, g_idx);

    const int n4 = (FLAT * N_MOVES) / 4;             // 2,170,144
    extract_idx_kernel<<<1184, 256>>>((const float4*)W, idx_ptr, n4);
    gather_kernel<<<BATCH / ROWS, 256>>>(x, idx_ptr, out);
}